// round 1
// baseline (speedup 1.0000x reference)
#include <cuda_runtime.h>

// NeuralFSM collapses to a discrete automaton:
//   state[n] in {0..7}  (s stays one-hot forever)
//   per iter: mask[dst] |= 1<<state[src]  (over all edges)
//             state[n] = table[mask[n]][state[n]],  mask[n] = 0
//   table[x][s] = argmax_t T[x,s,t]  (one-hot rows)

#define MAXN 100000
#define NSTATES 8

__device__ unsigned char g_state[MAXN];
__device__ unsigned int  g_mask[MAXN];
__device__ unsigned char g_table[256 * NSTATES];

static __device__ __forceinline__ int onehot_idx(float4 a, float4 b) {
    int st = 0;
    if (a.y > 0.5f) st = 1;
    if (a.z > 0.5f) st = 2;
    if (a.w > 0.5f) st = 3;
    if (b.x > 0.5f) st = 4;
    if (b.y > 0.5f) st = 5;
    if (b.z > 0.5f) st = 6;
    if (b.w > 0.5f) st = 7;
    return st;
}

__global__ void k_init(const float* __restrict__ s0, int n) {
    int i = blockIdx.x * blockDim.x + threadIdx.x;
    if (i >= n) return;
    const float4* p = (const float4*)(s0 + (size_t)i * 8);
    float4 a = p[0];
    float4 b = p[1];
    g_state[i] = (unsigned char)onehot_idx(a, b);
    g_mask[i] = 0u;
}

__global__ void k_table(const float* __restrict__ T) {
    int i = blockIdx.x * blockDim.x + threadIdx.x;
    if (i >= 256 * NSTATES) return;
    const float4* p = (const float4*)(T + (size_t)i * 8);
    float4 a = p[0];
    float4 b = p[1];
    g_table[i] = (unsigned char)onehot_idx(a, b);
}

// Edge pass: mask[dst] |= 1 << state[src].
// Check-before-atomic is safe: within this launch mask bits are monotone
// increasing and L1 is flushed at launch boundary, so a stale L1 read can only
// under-report set bits -> at worst a redundant atomicOr, never a missed set.
__global__ void k_edges(const int* __restrict__ src, const int* __restrict__ dst, int E) {
    int i = blockIdx.x * blockDim.x + threadIdx.x;
    int e0 = i * 4;
    if (e0 + 3 < E) {
        int4 s4 = *(const int4*)(src + e0);
        int4 d4 = *(const int4*)(dst + e0);
        unsigned b0 = 1u << g_state[s4.x];
        unsigned b1 = 1u << g_state[s4.y];
        unsigned b2 = 1u << g_state[s4.z];
        unsigned b3 = 1u << g_state[s4.w];
        if (!(g_mask[d4.x] & b0)) atomicOr(&g_mask[d4.x], b0);
        if (!(g_mask[d4.y] & b1)) atomicOr(&g_mask[d4.y], b1);
        if (!(g_mask[d4.z] & b2)) atomicOr(&g_mask[d4.z], b2);
        if (!(g_mask[d4.w] & b3)) atomicOr(&g_mask[d4.w], b3);
    } else {
        for (int e = e0; e < E; e++) {
            unsigned b = 1u << g_state[src[e]];
            if (!(g_mask[dst[e]] & b)) atomicOr(&g_mask[dst[e]], b);
        }
    }
}

__global__ void k_update(int n) {
    int i = blockIdx.x * blockDim.x + threadIdx.x;
    if (i >= n) return;
    unsigned m = g_mask[i];
    unsigned s = g_state[i];
    g_state[i] = g_table[(m << 3) | s];
    g_mask[i] = 0u;
}

__global__ void k_out(float* __restrict__ out, int n) {
    int i = blockIdx.x * blockDim.x + threadIdx.x;
    if (i >= n) return;
    int st = g_state[i];
    float4 a, b;
    a.x = (st == 0) ? 1.0f : 0.0f;
    a.y = (st == 1) ? 1.0f : 0.0f;
    a.z = (st == 2) ? 1.0f : 0.0f;
    a.w = (st == 3) ? 1.0f : 0.0f;
    b.x = (st == 4) ? 1.0f : 0.0f;
    b.y = (st == 5) ? 1.0f : 0.0f;
    b.z = (st == 6) ? 1.0f : 0.0f;
    b.w = (st == 7) ? 1.0f : 0.0f;
    float4* o = (float4*)(out + (size_t)i * 8);
    o[0] = a;
    o[1] = b;
}

extern "C" void kernel_launch(void* const* d_in, const int* in_sizes, int n_in,
                              void* d_out, int out_size) {
    const float* s0 = (const float*)d_in[0];
    const int*   ei = (const int*)d_in[1];
    const float* T  = (const float*)d_in[2];

    int N = in_sizes[0] / 8;   // 100000
    int E = in_sizes[1] / 2;   // 6400000
    const int* src = ei;
    const int* dst = ei + E;

    const int TB = 256;
    int nb_nodes = (N + TB - 1) / TB;
    int nE4 = (E + 3) / 4;
    int nb_edges = (nE4 + TB - 1) / TB;

    k_init<<<nb_nodes, TB>>>(s0, N);
    k_table<<<(256 * NSTATES + TB - 1) / TB, TB>>>(T);

    for (int it = 0; it < 20; it++) {
        k_edges<<<nb_edges, TB>>>(src, dst, E);
        k_update<<<nb_nodes, TB>>>(N);
    }

    k_out<<<nb_nodes, TB>>>((float*)d_out, N);
}